// round 8
// baseline (speedup 1.0000x reference)
#include <cuda_runtime.h>
#include <cuda_bf16.h>

// PackedAvgPool1d — fused streaming kernel, warp-local index prologue,
// host-dispatched fast path (batch <= 32) vs generic path.
//   blockDim = 384 flat; 4 rows per block, 3 warps per row; each thread owns
//   float4 columns c and c+96 (DIM=768 -> 192 float4/row).
//   Fast path: lane i holds seq_lens[i]; shfl-scan prefixes in registers;
//   row->batch via ballot+popc. No smem, no __syncthreads, 32-bit indexing.

#define POOL_D4   192
#define MAX_BATCH 1024
#define FULLMASK  0xFFFFFFFFu

__global__ void __launch_bounds__(384, 5) pool_kernel_fast(
    const float4* __restrict__ x,
    const int*    __restrict__ seq_lens,
    const int*    __restrict__ pK,
    const int*    __restrict__ pS,
    float4*       __restrict__ out,
    int batch, int n_rows)
{
    const int lane = threadIdx.x & 31;
    const int warp = threadIdx.x >> 5;

    const int K = pK ? __ldg(pK) : 2;
    const int S = pS ? __ldg(pS) : 2;

    const int row = blockIdx.x * 4 + warp / 3;
    const unsigned c = (unsigned)(warp % 3) * 32u + (unsigned)lane;  // 0..95

    // ---- warp-local prologue ----
    int L = (lane < batch) ? __ldg(&seq_lens[lane]) : 0;
    int yl = 0;
    if (L > 0) {
        int num = L - K; if (num < 0) num = 0;
        yl = (num + S - 1) / S + 1;
    }
    int xs = L, ys = yl;                       // inclusive scans
    #pragma unroll
    for (int d = 1; d < 32; d <<= 1) {
        const int nx = __shfl_up_sync(FULLMASK, xs, d);
        const int ny = __shfl_up_sync(FULLMASK, ys, d);
        if (lane >= d) { xs += nx; ys += ny; }
    }
    if (row >= n_rows) return;                 // row uniform per warp: whole warp exits
    const unsigned m = __ballot_sync(FULLMASK, ys <= row);
    const int b = __popc(m);
    const int ybase = (b > 0) ? __shfl_sync(FULLMASK, ys, b - 1) : 0;
    const int base  = (b > 0) ? __shfl_sync(FULLMASK, xs, b - 1) : 0;
    const int Lb    = __shfl_sync(FULLMASK, L, b);
    const int j     = row - ybase;

    const int p0 = j * S;
    int cnt = Lb - p0; if (cnt > K) cnt = K; if (cnt < 1) cnt = 1;

    const unsigned sbase = (unsigned)(base + p0) * POOL_D4 + c;  // 32-bit indexing
    float4 a0 = __ldcs(&x[sbase]);
    float4 a1 = __ldcs(&x[sbase + 96u]);

    if (cnt >= 2) {
        float4 b0 = __ldcs(&x[sbase + POOL_D4]);
        float4 b1 = __ldcs(&x[sbase + POOL_D4 + 96u]);
        if (cnt == 2) {
            a0.x = (a0.x + b0.x) * 0.5f; a0.y = (a0.y + b0.y) * 0.5f;
            a0.z = (a0.z + b0.z) * 0.5f; a0.w = (a0.w + b0.w) * 0.5f;
            a1.x = (a1.x + b1.x) * 0.5f; a1.y = (a1.y + b1.y) * 0.5f;
            a1.z = (a1.z + b1.z) * 0.5f; a1.w = (a1.w + b1.w) * 0.5f;
        } else {                               // general K (cnt > 2)
            a0.x += b0.x; a0.y += b0.y; a0.z += b0.z; a0.w += b0.w;
            a1.x += b1.x; a1.y += b1.y; a1.z += b1.z; a1.w += b1.w;
            for (int k = 2; k < cnt; ++k) {
                const float4 v0 = __ldcs(&x[sbase + (unsigned)k * POOL_D4]);
                const float4 v1 = __ldcs(&x[sbase + (unsigned)k * POOL_D4 + 96u]);
                a0.x += v0.x; a0.y += v0.y; a0.z += v0.z; a0.w += v0.w;
                a1.x += v1.x; a1.y += v1.y; a1.z += v1.z; a1.w += v1.w;
            }
            const float inv = 1.0f / (float)cnt;
            a0.x *= inv; a0.y *= inv; a0.z *= inv; a0.w *= inv;
            a1.x *= inv; a1.y *= inv; a1.z *= inv; a1.w *= inv;
        }
    }

    const unsigned obase = (unsigned)row * POOL_D4 + c;
    __stcs(&out[obase], a0);
    __stcs(&out[obase + 96u], a1);
}

// ---- generic path (batch > 32): block-shared prefix tables ----
__global__ void __launch_bounds__(384) pool_kernel_generic(
    const float4* __restrict__ x,
    const int*    __restrict__ seq_lens,
    const int*    __restrict__ pK,
    const int*    __restrict__ pS,
    float4*       __restrict__ out,
    int batch, int n_rows)
{
    __shared__ int s_xcu[MAX_BATCH + 1];
    __shared__ int s_ycu[MAX_BATCH + 1];

    const int lane = threadIdx.x & 31;
    const int warp = threadIdx.x >> 5;

    const int K = pK ? __ldg(pK) : 2;
    const int S = pS ? __ldg(pS) : 2;

    if (warp == 0) {
        int xoff = 0, yoff = 0;
        if (lane == 0) { s_xcu[0] = 0; s_ycu[0] = 0; }
        for (int chunk = 0; chunk < batch; chunk += 32) {
            const int i = chunk + lane;
            int L = (i < batch) ? __ldg(&seq_lens[i]) : 0;
            int yl = 0;
            if (L > 0) {
                int num = L - K; if (num < 0) num = 0;
                yl = (num + S - 1) / S + 1;
            }
            int xs = L, ys = yl;
            #pragma unroll
            for (int d = 1; d < 32; d <<= 1) {
                const int nx = __shfl_up_sync(FULLMASK, xs, d);
                const int ny = __shfl_up_sync(FULLMASK, ys, d);
                if (lane >= d) { xs += nx; ys += ny; }
            }
            if (i < batch) { s_xcu[i + 1] = xoff + xs; s_ycu[i + 1] = yoff + ys; }
            xoff += __shfl_sync(FULLMASK, xs, 31);
            yoff += __shfl_sync(FULLMASK, ys, 31);
        }
    }
    __syncthreads();

    const int row = blockIdx.x * 4 + warp / 3;
    if (row >= n_rows) return;
    const unsigned c = (unsigned)(warp % 3) * 32u + (unsigned)lane;

    int lo = 0, hi = batch;
    while (hi - lo > 1) {
        const int mid = (lo + hi) >> 1;
        if (s_ycu[mid] <= row) lo = mid; else hi = mid;
    }
    const int base = s_xcu[lo];
    const int Lb   = s_xcu[lo + 1] - base;
    const int j    = row - s_ycu[lo];

    const int p0 = j * S;
    int cnt = Lb - p0; if (cnt > K) cnt = K; if (cnt < 1) cnt = 1;

    const size_t sbase = (size_t)(base + p0) * POOL_D4 + c;
    float4 a0 = __ldcs(&x[sbase]);
    float4 a1 = __ldcs(&x[sbase + 96]);
    if (cnt >= 2) {
        float4 b0 = __ldcs(&x[sbase + POOL_D4]);
        float4 b1 = __ldcs(&x[sbase + POOL_D4 + 96]);
        if (cnt == 2) {
            a0.x = (a0.x + b0.x) * 0.5f; a0.y = (a0.y + b0.y) * 0.5f;
            a0.z = (a0.z + b0.z) * 0.5f; a0.w = (a0.w + b0.w) * 0.5f;
            a1.x = (a1.x + b1.x) * 0.5f; a1.y = (a1.y + b1.y) * 0.5f;
            a1.z = (a1.z + b1.z) * 0.5f; a1.w = (a1.w + b1.w) * 0.5f;
        } else {
            a0.x += b0.x; a0.y += b0.y; a0.z += b0.z; a0.w += b0.w;
            a1.x += b1.x; a1.y += b1.y; a1.z += b1.z; a1.w += b1.w;
            for (int k = 2; k < cnt; ++k) {
                const float4 v0 = __ldcs(&x[sbase + (size_t)k * POOL_D4]);
                const float4 v1 = __ldcs(&x[sbase + (size_t)k * POOL_D4 + 96]);
                a0.x += v0.x; a0.y += v0.y; a0.z += v0.z; a0.w += v0.w;
                a1.x += v1.x; a1.y += v1.y; a1.z += v1.z; a1.w += v1.w;
            }
            const float inv = 1.0f / (float)cnt;
            a0.x *= inv; a0.y *= inv; a0.z *= inv; a0.w *= inv;
            a1.x *= inv; a1.y *= inv; a1.z *= inv; a1.w *= inv;
        }
    }
    const size_t obase = (size_t)row * POOL_D4 + c;
    __stcs(&out[obase], a0);
    __stcs(&out[obase + 96], a1);
}

extern "C" void kernel_launch(void* const* d_in, const int* in_sizes, int n_in,
                              void* d_out, int out_size)
{
    const float4* x        = (const float4*)d_in[0];
    const int*    seq_lens = (const int*)d_in[1];
    const int*    pK       = (n_in >= 3) ? (const int*)d_in[2] : nullptr;
    const int*    pS       = (n_in >= 4) ? (const int*)d_in[3] : nullptr;
    float4*       out      = (float4*)d_out;

    const int batch  = in_sizes[1];
    const int n_rows = out_size / 768;
    if (n_rows <= 0) return;

    const int grid = (n_rows + 3) / 4;
    if (batch <= 32) {
        pool_kernel_fast<<<grid, 384>>>(x, seq_lens, pK, pS, out, batch, n_rows);
    } else {
        pool_kernel_generic<<<grid, 384>>>(x, seq_lens, pK, pS, out, batch, n_rows);
    }
}

// round 9
// speedup vs baseline: 1.0061x; 1.0061x over previous
#include <cuda_runtime.h>
#include <cuda_bf16.h>

// PackedAvgPool1d — fused streaming kernel, warp-local index prologue,
// host-dispatched fast path (batch <= 32) vs generic path.
//   blockDim = 384 flat; 4 rows per block, 3 warps per row; each thread owns
//   float4 columns c and c+96 (DIM=768 -> 192 float4/row).
//   Fast path: lane i holds seq_lens[i]; shfl-scan prefixes in registers;
//   row->batch via ballot+popc. No smem, no __syncthreads, 32-bit indexing.
//   Occupancy pinned to 4 blocks/SM: 5 blocks/SM measured SLOWER (R8: DRAM
//   76.7% vs 81.2% at 4 blocks — L1tex queue contention from redundant
//   prologues outweighs extra latency hiding).

#define POOL_D4   192
#define MAX_BATCH 1024
#define FULLMASK  0xFFFFFFFFu

__global__ void __launch_bounds__(384, 4) pool_kernel_fast(
    const float4* __restrict__ x,
    const int*    __restrict__ seq_lens,
    const int*    __restrict__ pK,
    const int*    __restrict__ pS,
    float4*       __restrict__ out,
    int batch, int n_rows)
{
    const int lane = threadIdx.x & 31;
    const int warp = threadIdx.x >> 5;

    const int K = pK ? __ldg(pK) : 2;
    const int S = pS ? __ldg(pS) : 2;

    const int row = blockIdx.x * 4 + warp / 3;
    const unsigned c = (unsigned)(warp % 3) * 32u + (unsigned)lane;  // 0..95

    // ---- warp-local prologue ----
    int L = (lane < batch) ? __ldg(&seq_lens[lane]) : 0;
    int yl = 0;
    if (L > 0) {
        int num = L - K; if (num < 0) num = 0;
        yl = (num + S - 1) / S + 1;
    }
    int xs = L, ys = yl;                       // inclusive scans
    #pragma unroll
    for (int d = 1; d < 32; d <<= 1) {
        const int nx = __shfl_up_sync(FULLMASK, xs, d);
        const int ny = __shfl_up_sync(FULLMASK, ys, d);
        if (lane >= d) { xs += nx; ys += ny; }
    }
    if (row >= n_rows) return;                 // row uniform per warp: whole warp exits
    const unsigned m = __ballot_sync(FULLMASK, ys <= row);
    const int b = __popc(m);
    const int ybase = (b > 0) ? __shfl_sync(FULLMASK, ys, b - 1) : 0;
    const int base  = (b > 0) ? __shfl_sync(FULLMASK, xs, b - 1) : 0;
    const int Lb    = __shfl_sync(FULLMASK, L, b);
    const int j     = row - ybase;

    const int p0 = j * S;
    int cnt = Lb - p0; if (cnt > K) cnt = K; if (cnt < 1) cnt = 1;

    const unsigned sbase = (unsigned)(base + p0) * POOL_D4 + c;  // 32-bit indexing
    float4 a0 = __ldcs(&x[sbase]);
    float4 a1 = __ldcs(&x[sbase + 96u]);

    if (cnt >= 2) {
        float4 b0 = __ldcs(&x[sbase + POOL_D4]);
        float4 b1 = __ldcs(&x[sbase + POOL_D4 + 96u]);
        if (cnt == 2) {
            a0.x = (a0.x + b0.x) * 0.5f; a0.y = (a0.y + b0.y) * 0.5f;
            a0.z = (a0.z + b0.z) * 0.5f; a0.w = (a0.w + b0.w) * 0.5f;
            a1.x = (a1.x + b1.x) * 0.5f; a1.y = (a1.y + b1.y) * 0.5f;
            a1.z = (a1.z + b1.z) * 0.5f; a1.w = (a1.w + b1.w) * 0.5f;
        } else {                               // general K (cnt > 2)
            a0.x += b0.x; a0.y += b0.y; a0.z += b0.z; a0.w += b0.w;
            a1.x += b1.x; a1.y += b1.y; a1.z += b1.z; a1.w += b1.w;
            for (int k = 2; k < cnt; ++k) {
                const float4 v0 = __ldcs(&x[sbase + (unsigned)k * POOL_D4]);
                const float4 v1 = __ldcs(&x[sbase + (unsigned)k * POOL_D4 + 96u]);
                a0.x += v0.x; a0.y += v0.y; a0.z += v0.z; a0.w += v0.w;
                a1.x += v1.x; a1.y += v1.y; a1.z += v1.z; a1.w += v1.w;
            }
            const float inv = 1.0f / (float)cnt;
            a0.x *= inv; a0.y *= inv; a0.z *= inv; a0.w *= inv;
            a1.x *= inv; a1.y *= inv; a1.z *= inv; a1.w *= inv;
        }
    }

    const unsigned obase = (unsigned)row * POOL_D4 + c;
    __stcs(&out[obase], a0);
    __stcs(&out[obase + 96u], a1);
}

// ---- generic path (batch > 32): block-shared prefix tables ----
__global__ void __launch_bounds__(384) pool_kernel_generic(
    const float4* __restrict__ x,
    const int*    __restrict__ seq_lens,
    const int*    __restrict__ pK,
    const int*    __restrict__ pS,
    float4*       __restrict__ out,
    int batch, int n_rows)
{
    __shared__ int s_xcu[MAX_BATCH + 1];
    __shared__ int s_ycu[MAX_BATCH + 1];

    const int lane = threadIdx.x & 31;
    const int warp = threadIdx.x >> 5;

    const int K = pK ? __ldg(pK) : 2;
    const int S = pS ? __ldg(pS) : 2;

    if (warp == 0) {
        int xoff = 0, yoff = 0;
        if (lane == 0) { s_xcu[0] = 0; s_ycu[0] = 0; }
        for (int chunk = 0; chunk < batch; chunk += 32) {
            const int i = chunk + lane;
            int L = (i < batch) ? __ldg(&seq_lens[i]) : 0;
            int yl = 0;
            if (L > 0) {
                int num = L - K; if (num < 0) num = 0;
                yl = (num + S - 1) / S + 1;
            }
            int xs = L, ys = yl;
            #pragma unroll
            for (int d = 1; d < 32; d <<= 1) {
                const int nx = __shfl_up_sync(FULLMASK, xs, d);
                const int ny = __shfl_up_sync(FULLMASK, ys, d);
                if (lane >= d) { xs += nx; ys += ny; }
            }
            if (i < batch) { s_xcu[i + 1] = xoff + xs; s_ycu[i + 1] = yoff + ys; }
            xoff += __shfl_sync(FULLMASK, xs, 31);
            yoff += __shfl_sync(FULLMASK, ys, 31);
        }
    }
    __syncthreads();

    const int row = blockIdx.x * 4 + warp / 3;
    if (row >= n_rows) return;
    const unsigned c = (unsigned)(warp % 3) * 32u + (unsigned)lane;

    int lo = 0, hi = batch;
    while (hi - lo > 1) {
        const int mid = (lo + hi) >> 1;
        if (s_ycu[mid] <= row) lo = mid; else hi = mid;
    }
    const int base = s_xcu[lo];
    const int Lb   = s_xcu[lo + 1] - base;
    const int j    = row - s_ycu[lo];

    const int p0 = j * S;
    int cnt = Lb - p0; if (cnt > K) cnt = K; if (cnt < 1) cnt = 1;

    const size_t sbase = (size_t)(base + p0) * POOL_D4 + c;
    float4 a0 = __ldcs(&x[sbase]);
    float4 a1 = __ldcs(&x[sbase + 96]);
    if (cnt >= 2) {
        float4 b0 = __ldcs(&x[sbase + POOL_D4]);
        float4 b1 = __ldcs(&x[sbase + POOL_D4 + 96]);
        if (cnt == 2) {
            a0.x = (a0.x + b0.x) * 0.5f; a0.y = (a0.y + b0.y) * 0.5f;
            a0.z = (a0.z + b0.z) * 0.5f; a0.w = (a0.w + b0.w) * 0.5f;
            a1.x = (a1.x + b1.x) * 0.5f; a1.y = (a1.y + b1.y) * 0.5f;
            a1.z = (a1.z + b1.z) * 0.5f; a1.w = (a1.w + b1.w) * 0.5f;
        } else {
            a0.x += b0.x; a0.y += b0.y; a0.z += b0.z; a0.w += b0.w;
            a1.x += b1.x; a1.y += b1.y; a1.z += b1.z; a1.w += b1.w;
            for (int k = 2; k < cnt; ++k) {
                const float4 v0 = __ldcs(&x[sbase + (size_t)k * POOL_D4]);
                const float4 v1 = __ldcs(&x[sbase + (size_t)k * POOL_D4 + 96]);
                a0.x += v0.x; a0.y += v0.y; a0.z += v0.z; a0.w += v0.w;
                a1.x += v1.x; a1.y += v1.y; a1.z += v1.z; a1.w += v1.w;
            }
            const float inv = 1.0f / (float)cnt;
            a0.x *= inv; a0.y *= inv; a0.z *= inv; a0.w *= inv;
            a1.x *= inv; a1.y *= inv; a1.z *= inv; a1.w *= inv;
        }
    }
    const size_t obase = (size_t)row * POOL_D4 + c;
    __stcs(&out[obase], a0);
    __stcs(&out[obase + 96], a1);
}

extern "C" void kernel_launch(void* const* d_in, const int* in_sizes, int n_in,
                              void* d_out, int out_size)
{
    const float4* x        = (const float4*)d_in[0];
    const int*    seq_lens = (const int*)d_in[1];
    const int*    pK       = (n_in >= 3) ? (const int*)d_in[2] : nullptr;
    const int*    pS       = (n_in >= 4) ? (const int*)d_in[3] : nullptr;
    float4*       out      = (float4*)d_out;

    const int batch  = in_sizes[1];
    const int n_rows = out_size / 768;
    if (n_rows <= 0) return;

    const int grid = (n_rows + 3) / 4;
    if (batch <= 32) {
        pool_kernel_fast<<<grid, 384>>>(x, seq_lens, pK, pS, out, batch, n_rows);
    } else {
        pool_kernel_generic<<<grid, 384>>>(x, seq_lens, pK, pS, out, batch, n_rows);
    }
}